// round 2
// baseline (speedup 1.0000x reference)
#include <cuda_runtime.h>
#include <cuda_bf16.h>
#include <cstdint>

// ---------------- problem constants ----------------
#define NPTS        64
#define NBINS       64
#define KDIM        192      // 3 * NBINS
#define FC          64       // feat_channels
#define TILE_P      64       // pillars per block tile
#define NTHREADS    256
#define MCAP        100000
#define Z_MIN_F     (-3.0f)
#define INV_BIN     16.0f    // 1 / 0.0625  (exact)
#define EPS_MEAN    1e-5f
#define EPS_BN      1e-5f

// shared layout (floats):
//   Ws   [KDIM][FC]           12288
//   A    [KDIM][TILE_P]       12288   (k' = comp*64 + bin; column = pillar)
//   stg  union {stage, red}    2048
//   npc  64 ints                 64
#define SM_WS    0
#define SM_A     12288
#define SM_STG   24576
#define SM_NPC   26624
#define SMEM_FLOATS 26688
#define SMEM_BYTES  (SMEM_FLOATS * 4)   // 106752

// ---------------- global scratch ----------------
__device__ float4 g_X[MCAP * (FC / 4)];   // x = hist @ W.T + b   [M][64]
__device__ float  g_sum[FC];
__device__ float  g_sqs[FC];
__device__ float  g_scale[FC];
__device__ float  g_shift[FC];

// ---------------- f32x2 helpers ----------------
__device__ __forceinline__ unsigned long long pack2(float a, float b) {
    unsigned long long d;
    asm("mov.b64 %0, {%1, %2};" : "=l"(d) : "r"(__float_as_uint(a)), "r"(__float_as_uint(b)));
    return d;
}
__device__ __forceinline__ unsigned long long pack1(float a) {
    unsigned long long d;
    asm("mov.b64 %0, {%1, %1};" : "=l"(d) : "r"(__float_as_uint(a)));
    return d;
}
__device__ __forceinline__ void fma2(unsigned long long& acc, unsigned long long a, unsigned long long b) {
    asm("fma.rn.f32x2 %0, %1, %2, %0;" : "+l"(acc) : "l"(a), "l"(b));
}
__device__ __forceinline__ void unpack2(unsigned long long v, float& lo, float& hi) {
    unsigned int l, h;
    asm("mov.b64 {%0, %1}, %2;" : "=r"(l), "=r"(h) : "l"(v));
    lo = __uint_as_float(l);
    hi = __uint_as_float(h);
}

// ---------------- kernel 0: zero the BN accumulators ----------------
__global__ void zero_kernel() {
    int t = threadIdx.x;
    if (t < FC) { g_sum[t] = 0.0f; g_sqs[t] = 0.0f; }
}

// ---------------- kernel 1: fused hist + GEMM + BN partial sums ----------------
__global__ void __launch_bounds__(NTHREADS)
main_kernel(const float* __restrict__ feat,
            const int*   __restrict__ nump,
            const float* __restrict__ W,
            const float* __restrict__ bbias,
            int M)
{
    extern __shared__ float sm[];
    float* Ws  = sm + SM_WS;       // [192][64]
    float* A   = sm + SM_A;        // [192][64]
    float* stg = sm + SM_STG;      // staging / reduction union
    int*   npc = (int*)(sm + SM_NPC);

    const int tid  = threadIdx.x;
    const int base = blockIdx.x * TILE_P;

    // ---- load W (reordered: Ws[(comp*64+bin)*64 + c] = W[c*192 + bin*3 + comp]) & zero A ----
    #pragma unroll 4
    for (int i = tid; i < KDIM * FC; i += NTHREADS) {
        int c    = i & 63;
        int kp   = i >> 6;
        int comp = kp >> 6;
        int bin  = kp & 63;
        Ws[i] = W[c * KDIM + bin * 3 + comp];
        A[i]  = 0.0f;
    }
    if (tid < TILE_P) {
        int gp = base + tid;
        npc[tid] = (gp < M) ? nump[gp] : 0;
    }
    __syncthreads();

    // ---- histogram: 8 chunks of 8 points, staged through shared ----
    float2* stage = (float2*)stg;   // [64 pillars][9] (8 points + pad)
    for (int ch = 0; ch < 8; ch++) {
        #pragma unroll
        for (int u = 0; u < 2; u++) {
            int i = tid + u * NTHREADS;   // 0..511
            int p = i >> 3;
            int j = i & 7;
            int gp = base + p;
            float2 v = make_float2(0.0f, 0.0f);
            if (gp < M) {
                int n = ch * 8 + j;
                v = *(const float2*)(feat + (size_t)gp * (NPTS * 4) + n * 4 + 2); // (z, r)
            }
            stage[p * 9 + j] = v;
        }
        __syncthreads();
        if (tid < TILE_P) {
            int np = npc[tid];
            #pragma unroll
            for (int j = 0; j < 8; j++) {
                int n = ch * 8 + j;
                if (n >= np) break;   // valid points form a prefix
                float2 v = stage[tid * 9 + j];
                float z = v.x, r = v.y;
                int bin = (int)((z - Z_MIN_F) * INV_BIN);   // trunc-toward-zero == astype(int32)
                bin = max(0, min(NBINS - 1, bin));
                float* pc = &A[bin * TILE_P + tid];         // conflict-free: bank = tid mod 32
                pc[0]                += 1.0f;               // count
                pc[NBINS * TILE_P]   += z;                  // sum_z
                pc[2 * NBINS*TILE_P] += r;                  // sum_r
            }
        }
        __syncthreads();
    }

    // ---- convert sums to means ----
    #pragma unroll 4
    for (int i = tid; i < NBINS * TILE_P; i += NTHREADS) {
        float cnt = A[i];
        float inv = __frcp_rn(cnt + EPS_MEAN);
        A[i + NBINS * TILE_P]     *= inv;
        A[i + 2 * NBINS * TILE_P] *= inv;
    }
    __syncthreads();

    // ---- GEMM: x[64 pillars][64 ch] = A^T @ Ws + b  (thread = 4 pillars x 4 channels) ----
    const int colT = tid & 15;
    const int rowT = tid >> 4;
    const int cb = colT * 4;
    const int pb = rowT * 4;

    float4 bv = *(const float4*)(bbias + cb);
    unsigned long long bp0 = pack2(bv.x, bv.y);
    unsigned long long bp1 = pack2(bv.z, bv.w);
    unsigned long long acc[4][2];
    #pragma unroll
    for (int p = 0; p < 4; p++) { acc[p][0] = bp0; acc[p][1] = bp1; }

    const float* Arow = A  + pb;
    const float* Wrow = Ws + cb;
    #pragma unroll 4
    for (int k = 0; k < KDIM; k++) {
        float4 a4 = *(const float4*)(Arow + k * TILE_P);
        float4 w4 = *(const float4*)(Wrow + k * FC);
        unsigned long long w01 = pack2(w4.x, w4.y);
        unsigned long long w23 = pack2(w4.z, w4.w);
        unsigned long long aa;
        aa = pack1(a4.x); fma2(acc[0][0], aa, w01); fma2(acc[0][1], aa, w23);
        aa = pack1(a4.y); fma2(acc[1][0], aa, w01); fma2(acc[1][1], aa, w23);
        aa = pack1(a4.z); fma2(acc[2][0], aa, w01); fma2(acc[2][1], aa, w23);
        aa = pack1(a4.w); fma2(acc[3][0], aa, w01); fma2(acc[3][1], aa, w23);
    }

    // ---- epilogue: store x, accumulate BN partials ----
    float s0 = 0, s1 = 0, s2 = 0, s3 = 0;
    float q0 = 0, q1 = 0, q2 = 0, q3 = 0;
    #pragma unroll
    for (int p = 0; p < 4; p++) {
        float x0, x1, x2, x3;
        unpack2(acc[p][0], x0, x1);
        unpack2(acc[p][1], x2, x3);
        int gp = base + pb + p;
        if (gp < M) {
            g_X[gp * (FC / 4) + (cb >> 2)] = make_float4(x0, x1, x2, x3);
            s0 += x0; q0 += x0 * x0;
            s1 += x1; q1 += x1 * x1;
            s2 += x2; q2 += x2 * x2;
            s3 += x3; q3 += x3 * x3;
        }
    }
    __syncthreads();   // stage region is dead; reuse as reduction buffer
    float* redS = stg;          // [16][64]
    float* redQ = stg + 1024;   // [16][64]
    *(float4*)&redS[rowT * FC + cb] = make_float4(s0, s1, s2, s3);
    *(float4*)&redQ[rowT * FC + cb] = make_float4(q0, q1, q2, q3);
    __syncthreads();
    if (tid < FC) {
        float ts = 0.0f, tq = 0.0f;
        #pragma unroll
        for (int r2 = 0; r2 < 16; r2++) {
            ts += redS[r2 * FC + tid];
            tq += redQ[r2 * FC + tid];
        }
        atomicAdd(&g_sum[tid], ts);
        atomicAdd(&g_sqs[tid], tq);
    }
}

// ---------------- kernel 2: finalize BN scale/shift ----------------
__global__ void finalize_kernel(const float* __restrict__ gamma,
                                const float* __restrict__ beta,
                                int M)
{
    int c = threadIdx.x;
    if (c < FC) {
        float invM = 1.0f / (float)M;
        float mu   = g_sum[c] * invM;
        float var  = g_sqs[c] * invM - mu * mu;
        var = fmaxf(var, 0.0f);
        float sc = gamma[c] * rsqrtf(var + EPS_BN);
        g_scale[c] = sc;
        g_shift[c] = beta[c] - mu * sc;
    }
}

// ---------------- kernel 3: normalize + ReLU ----------------
__global__ void __launch_bounds__(256)
apply_kernel(float4* __restrict__ out, int M)
{
    int i = blockIdx.x * blockDim.x + threadIdx.x;   // over M*16 float4s
    if (i >= M * (FC / 4)) return;
    float4 x  = g_X[i];
    int cb = (i & 15) * 4;
    float4 sc = *(const float4*)&g_scale[cb];
    float4 sh = *(const float4*)&g_shift[cb];
    float4 r;
    r.x = fmaxf(fmaf(x.x, sc.x, sh.x), 0.0f);
    r.y = fmaxf(fmaf(x.y, sc.y, sh.y), 0.0f);
    r.z = fmaxf(fmaf(x.z, sc.z, sh.z), 0.0f);
    r.w = fmaxf(fmaf(x.w, sc.w, sh.w), 0.0f);
    out[i] = r;
}

// ---------------- launch ----------------
extern "C" void kernel_launch(void* const* d_in, const int* in_sizes, int n_in,
                              void* d_out, int out_size)
{
    const float* feat  = (const float*)d_in[0];
    const int*   nump  = (const int*)  d_in[1];
    // d_in[2] = coors (unused by the reference math)
    const float* W     = (const float*)d_in[3];
    const float* bbias = (const float*)d_in[4];
    const float* gamma = (const float*)d_in[5];
    const float* beta  = (const float*)d_in[6];
    float4* out = (float4*)d_out;

    int M = in_sizes[1];
    if (M > MCAP) M = MCAP;

    cudaFuncSetAttribute(main_kernel, cudaFuncAttributeMaxDynamicSharedMemorySize, SMEM_BYTES);

    zero_kernel<<<1, 64>>>();
    int tiles = (M + TILE_P - 1) / TILE_P;
    main_kernel<<<tiles, NTHREADS, SMEM_BYTES>>>(feat, nump, W, bbias, M);
    finalize_kernel<<<1, 64>>>(gamma, beta, M);
    int n4 = M * (FC / 4);
    apply_kernel<<<(n4 + 255) / 256, 256>>>(out, M);
}

// round 3
// speedup vs baseline: 1.1820x; 1.1820x over previous
#include <cuda_runtime.h>
#include <cuda_bf16.h>
#include <cstdint>

// ---------------- problem constants ----------------
#define NPTS        64
#define NBINS       64
#define KDIM        192      // 3 * NBINS
#define FC          64       // feat_channels
#define TILE_P      64       // pillars per block tile
#define NTHREADS    256
#define MCAP        100000
#define Z_MIN_F     (-3.0f)
#define INV_BIN     16.0f    // 1 / 0.0625 (exact)
#define EPS_MEAN    1e-5f
#define EPS_BN      1e-5f

// W shared pitch: 193 (odd => bank = (c + k) mod 32, no pileup; rows not 16B
// aligned so W is staged with scalar STS)
#define WG_PITCH 193

// shared layout (floats):
//   Wg  [64][193]   12352   (native gmem layout, padded)
//   A   [192][64]   12288   (k' = comp*64 + bin; column = pillar)
//   stg union{stage,red} 2048
//   npc 64 ints        64
#define SM_WG    0
#define SM_A     12352
#define SM_STG   24640
#define SM_NPC   26688
#define SMEM_FLOATS 26752
#define SMEM_BYTES  (SMEM_FLOATS * 4)   // 107008

// ---------------- global scratch ----------------
__device__ float4 g_X[MCAP * (FC / 4)];   // x = hist @ W.T + b   [M][64]
__device__ float  g_sum[FC];              // zero-initialized .bss
__device__ float  g_sqs[FC];
__device__ float  g_scale[FC];
__device__ float  g_shift[FC];

// ---------------- f32x2 helpers ----------------
typedef unsigned long long u64;
__device__ __forceinline__ u64 pack2(float a, float b) {
    u64 d;
    asm("mov.b64 %0, {%1, %2};" : "=l"(d) : "r"(__float_as_uint(a)), "r"(__float_as_uint(b)));
    return d;
}
__device__ __forceinline__ u64 pack1(float a) {
    u64 d;
    asm("mov.b64 %0, {%1, %1};" : "=l"(d) : "r"(__float_as_uint(a)));
    return d;
}
__device__ __forceinline__ void fma2(u64& acc, u64 a, u64 b) {
    asm("fma.rn.f32x2 %0, %1, %2, %0;" : "+l"(acc) : "l"(a), "l"(b));
}
__device__ __forceinline__ void unpack2(u64 v, float& lo, float& hi) {
    unsigned int l, h;
    asm("mov.b64 {%0, %1}, %2;" : "=r"(l), "=r"(h) : "l"(v));
    lo = __uint_as_float(l);
    hi = __uint_as_float(h);
}

// ---------------- kernel 1: fused hist + GEMM + BN partial sums ----------------
__global__ void __launch_bounds__(NTHREADS)
main_kernel(const float* __restrict__ feat,
            const int*   __restrict__ nump,
            const float* __restrict__ W,
            const float* __restrict__ bbias,
            int M)
{
    extern __shared__ float sm[];
    float* Wg  = sm + SM_WG;       // [64][193]
    float* A   = sm + SM_A;        // [192][64]
    float* stg = sm + SM_STG;
    int*   npc = (int*)(sm + SM_NPC);

    const int tid  = threadIdx.x;
    const int base = blockIdx.x * TILE_P;

    // ---- zero A (vectorized) ----
    {
        float4 z4 = make_float4(0.f, 0.f, 0.f, 0.f);
        float4* A4 = (float4*)A;
        #pragma unroll
        for (int i = tid; i < (KDIM * TILE_P) / 4; i += NTHREADS) A4[i] = z4;
    }

    // ---- W load: fully coalesced LDG.128, stored in native [c][k] layout ----
    {
        const float4* W4 = (const float4*)W;
        #pragma unroll
        for (int i = tid; i < (FC * KDIM) / 4; i += NTHREADS) {
            float4 v = W4[i];                 // W row = 192 floats = 48 float4 (never straddles)
            int c = i / 48;
            int k = (i - c * 48) * 4;
            float* dst = Wg + c * WG_PITCH + k;
            dst[0] = v.x; dst[1] = v.y; dst[2] = v.z; dst[3] = v.w;
        }
    }
    if (tid < TILE_P) {
        int gp = base + tid;
        npc[tid] = (gp < M) ? nump[gp] : 0;
    }
    __syncthreads();

    // ---- histogram: 8 chunks of 8 points, staged through shared ----
    float2* stage = (float2*)stg;   // [64 pillars][9] (8 points + pad) = 1152 floats
    for (int ch = 0; ch < 8; ch++) {
        #pragma unroll
        for (int u = 0; u < 2; u++) {
            int i = tid + u * NTHREADS;   // 0..511
            int p = i >> 3;
            int j = i & 7;
            int gp = base + p;
            float2 v = make_float2(0.0f, 0.0f);
            if (gp < M) {
                int n = ch * 8 + j;
                v = *(const float2*)(feat + (size_t)gp * (NPTS * 4) + n * 4 + 2); // (z, r)
            }
            stage[p * 9 + j] = v;
        }
        __syncthreads();
        if (tid < TILE_P) {
            int np = npc[tid];
            #pragma unroll
            for (int j = 0; j < 8; j++) {
                if (ch * 8 + j < np) {            // predicated, chains pipeline
                    float2 v = stage[tid * 9 + j];
                    float z = v.x, r = v.y;
                    int bin = (int)((z - Z_MIN_F) * INV_BIN);   // trunc == astype(int32)
                    bin = max(0, min(NBINS - 1, bin));
                    float* pc = &A[bin * TILE_P + tid];         // bank = tid mod 32
                    pc[0]                  += 1.0f;             // count
                    pc[NBINS * TILE_P]     += z;                // sum_z
                    pc[2 * NBINS * TILE_P] += r;                // sum_r
                }
            }
        }
        __syncthreads();
    }

    // ---- convert sums to means ----
    #pragma unroll 4
    for (int i = tid; i < NBINS * TILE_P; i += NTHREADS) {
        float cnt = A[i];
        float inv = __frcp_rn(cnt + EPS_MEAN);
        A[i + NBINS * TILE_P]     *= inv;
        A[i + 2 * NBINS * TILE_P] *= inv;
    }
    __syncthreads();

    // ---- GEMM: thread = 8 pillars (4 f32x2 pairs) x 2 channels ----
    const int lane = tid & 31;
    const int wid  = tid >> 5;
    const int c0   = lane * 2;      // channels c0, c0+1
    const int p0   = wid * 8;       // pillars p0..p0+7

    u64 acc[4][2];
    {
        u64 b0 = pack1(bbias[c0]);
        u64 b1 = pack1(bbias[c0 + 1]);
        #pragma unroll
        for (int pp = 0; pp < 4; pp++) { acc[pp][0] = b0; acc[pp][1] = b1; }
    }

    const float* w0p = Wg + c0 * WG_PITCH;
    const float* w1p = w0p + WG_PITCH;
    #pragma unroll
    for (int comp = 0; comp < 3; comp++) {
        const float* aB  = A + comp * (NBINS * TILE_P) + p0;
        const float* wB0 = w0p + comp;
        const float* wB1 = w1p + comp;
        #pragma unroll 4
        for (int bin = 0; bin < NBINS; bin++) {
            float4 aLo = *(const float4*)(aB + bin * TILE_P);       // p0..p0+3 (broadcast)
            float4 aHi = *(const float4*)(aB + bin * TILE_P + 4);   // p0+4..p0+7
            u64 a01 = pack2(aLo.x, aLo.y);
            u64 a23 = pack2(aLo.z, aLo.w);
            u64 a45 = pack2(aHi.x, aHi.y);
            u64 a67 = pack2(aHi.z, aHi.w);
            u64 wd0 = pack1(wB0[bin * 3]);
            u64 wd1 = pack1(wB1[bin * 3]);
            fma2(acc[0][0], a01, wd0);
            fma2(acc[1][0], a23, wd0);
            fma2(acc[2][0], a45, wd0);
            fma2(acc[3][0], a67, wd0);
            fma2(acc[0][1], a01, wd1);
            fma2(acc[1][1], a23, wd1);
            fma2(acc[2][1], a45, wd1);
            fma2(acc[3][1], a67, wd1);
        }
    }

    // ---- epilogue: store x (coalesced float2), accumulate BN partials ----
    float s0 = 0.f, s1 = 0.f, q0 = 0.f, q1 = 0.f;
    float2* gX2 = (float2*)g_X;
    #pragma unroll
    for (int p = 0; p < 8; p++) {
        float lo, hi, x0, x1;
        unpack2(acc[p >> 1][0], lo, hi); x0 = (p & 1) ? hi : lo;
        unpack2(acc[p >> 1][1], lo, hi); x1 = (p & 1) ? hi : lo;
        int gp = base + p0 + p;
        if (gp < M) {
            gX2[gp * (FC / 2) + lane] = make_float2(x0, x1);
            s0 += x0; q0 += x0 * x0;
            s1 += x1; q1 += x1 * x1;
        }
    }
    __syncthreads();   // stage region is dead; reuse as reduction buffer
    float2* redS = (float2*)stg;          // [8 warps][32 lanes]
    float2* redQ = redS + 256;
    redS[wid * 32 + lane] = make_float2(s0, s1);
    redQ[wid * 32 + lane] = make_float2(q0, q1);
    __syncthreads();
    if (tid < FC) {
        int l = tid >> 1, h = tid & 1;
        float ts = 0.f, tq = 0.f;
        #pragma unroll
        for (int w = 0; w < 8; w++) {
            float2 vs = redS[w * 32 + l];
            float2 vq = redQ[w * 32 + l];
            ts += h ? vs.y : vs.x;
            tq += h ? vq.y : vq.x;
        }
        atomicAdd(&g_sum[tid], ts);
        atomicAdd(&g_sqs[tid], tq);
    }
}

// ---------------- kernel 2: finalize BN scale/shift ----------------
__global__ void finalize_kernel(const float* __restrict__ gamma,
                                const float* __restrict__ beta,
                                int M)
{
    int c = threadIdx.x;
    if (c < FC) {
        float invM = 1.0f / (float)M;
        float mu   = g_sum[c] * invM;
        float var  = g_sqs[c] * invM - mu * mu;
        var = fmaxf(var, 0.0f);
        float sc = gamma[c] * rsqrtf(var + EPS_BN);
        g_scale[c] = sc;
        g_shift[c] = beta[c] - mu * sc;
    }
}

// ---------------- kernel 3: normalize + ReLU (MLP=4) + reset accumulators ----------------
__global__ void __launch_bounds__(256)
apply_kernel(float4* __restrict__ out, int M)
{
    int n4 = M * (FC / 4);
    int gid = blockIdx.x * blockDim.x + threadIdx.x;
    int stride = gridDim.x * blockDim.x;

    float4 x[4];
    int idx[4];
    #pragma unroll
    for (int u = 0; u < 4; u++) {
        int i = gid + u * stride;
        idx[u] = i;
        if (i < n4) x[u] = g_X[i];
    }
    #pragma unroll
    for (int u = 0; u < 4; u++) {
        int i = idx[u];
        if (i < n4) {
            int cb = (i & 15) * 4;
            float4 sc = *(const float4*)&g_scale[cb];
            float4 sh = *(const float4*)&g_shift[cb];
            float4 r;
            r.x = fmaxf(fmaf(x[u].x, sc.x, sh.x), 0.0f);
            r.y = fmaxf(fmaf(x[u].y, sc.y, sh.y), 0.0f);
            r.z = fmaxf(fmaf(x[u].z, sc.z, sh.z), 0.0f);
            r.w = fmaxf(fmaf(x[u].w, sc.w, sh.w), 0.0f);
            out[i] = r;
        }
    }
    // reset BN accumulators for the next replay (deterministic; finalize already consumed them)
    if (blockIdx.x == 0 && threadIdx.x < FC) {
        g_sum[threadIdx.x] = 0.0f;
        g_sqs[threadIdx.x] = 0.0f;
    }
}

// ---------------- launch ----------------
extern "C" void kernel_launch(void* const* d_in, const int* in_sizes, int n_in,
                              void* d_out, int out_size)
{
    const float* feat  = (const float*)d_in[0];
    const int*   nump  = (const int*)  d_in[1];
    // d_in[2] = coors (unused by the reference math)
    const float* W     = (const float*)d_in[3];
    const float* bbias = (const float*)d_in[4];
    const float* gamma = (const float*)d_in[5];
    const float* beta  = (const float*)d_in[6];
    float4* out = (float4*)d_out;

    int M = in_sizes[1];
    if (M > MCAP) M = MCAP;

    cudaFuncSetAttribute(main_kernel, cudaFuncAttributeMaxDynamicSharedMemorySize, SMEM_BYTES);

    int tiles = (M + TILE_P - 1) / TILE_P;
    main_kernel<<<tiles, NTHREADS, SMEM_BYTES>>>(feat, nump, W, bbias, M);
    finalize_kernel<<<1, 64>>>(gamma, beta, M);
    int n4 = M * (FC / 4);
    int threads_needed = (n4 + 3) / 4;
    int blocks = (threads_needed + 255) / 256;
    apply_kernel<<<blocks, 256>>>(out, M);
}

// round 4
// speedup vs baseline: 1.6408x; 1.3882x over previous
#include <cuda_runtime.h>
#include <cuda_bf16.h>
#include <cstdint>

// ---------------- problem constants ----------------
#define NPTS        64
#define NBINS       64
#define KDIM        192
#define FC          64
#define TILE_P      64
#define NTHREADS    256
#define MCAP        100000
#define Z_MIN_F     (-3.0f)
#define INV_BIN     16.0f
#define EPS_MEAN    1e-5f
#define EPS_BN      1e-5f

#define WG_PITCH 193

// shared layout (floats):
//   Wg    [64][193]                 12352  @ 0
//   A     [192][64]                 12288  @ 12352
//   stage 2 bufs x (z+r) x [64][9]   2304  @ 24640   (also BN-reduce overlay)
//   npc   64 ints                      64  @ 26944
#define SM_WG    0
#define SM_A     12352
#define SM_STG   24640
#define SM_NPC   26944
#define SMEM_FLOATS 27008
#define SMEM_BYTES  (SMEM_FLOATS * 4)   // 108032 -> 2 CTAs/SM (216KB <= 228KB)

// ---------------- global scratch ----------------
__device__ float4 g_X[MCAP * (FC / 4)];
__device__ float  g_sum[FC];
__device__ float  g_sqs[FC];
__device__ float  g_scale[FC];
__device__ float  g_shift[FC];

// ---------------- f32x2 helpers ----------------
typedef unsigned long long u64;
__device__ __forceinline__ u64 pack2(float a, float b) {
    u64 d;
    asm("mov.b64 %0, {%1, %2};" : "=l"(d) : "r"(__float_as_uint(a)), "r"(__float_as_uint(b)));
    return d;
}
__device__ __forceinline__ u64 pack1(float a) {
    u64 d;
    asm("mov.b64 %0, {%1, %1};" : "=l"(d) : "r"(__float_as_uint(a)));
    return d;
}
__device__ __forceinline__ void fma2(u64& acc, u64 a, u64 b) {
    asm("fma.rn.f32x2 %0, %1, %2, %0;" : "+l"(acc) : "l"(a), "l"(b));
}
__device__ __forceinline__ void unpack2(u64 v, float& lo, float& hi) {
    unsigned int l, h;
    asm("mov.b64 {%0, %1}, %2;" : "=r"(l), "=r"(h) : "l"(v));
    lo = __uint_as_float(l);
    hi = __uint_as_float(h);
}

// ---------------- kernel 1: fused hist + GEMM + BN partials ----------------
__global__ void __launch_bounds__(NTHREADS, 2)
main_kernel(const float* __restrict__ feat,
            const int*   __restrict__ nump,
            const float* __restrict__ W,
            const float* __restrict__ bbias,
            int M)
{
    extern __shared__ float sm[];
    float* Wg  = sm + SM_WG;
    float* A   = sm + SM_A;
    float* stg = sm + SM_STG;
    int*   npc = (int*)(sm + SM_NPC);

    const int tid  = threadIdx.x;
    const int base = blockIdx.x * TILE_P;

    // ---- zero A ----
    {
        float4 z4 = make_float4(0.f, 0.f, 0.f, 0.f);
        float4* A4 = (float4*)A;
        #pragma unroll
        for (int i = tid; i < (KDIM * TILE_P) / 4; i += NTHREADS) A4[i] = z4;
    }
    if (tid < TILE_P) {
        int gp = base + tid;
        npc[tid] = (gp < M) ? nump[gp] : 0;
    }
    // ---- W: coalesced LDG.128, native [c][k] layout, pitch 193 ----
    {
        const float4* W4 = (const float4*)W;
        #pragma unroll
        for (int i = tid; i < (FC * KDIM) / 4; i += NTHREADS) {
            float4 v = W4[i];
            int c = i / 48;
            int k = (i - c * 48) * 4;
            float* dst = Wg + c * WG_PITCH + k;
            dst[0] = v.x; dst[1] = v.y; dst[2] = v.z; dst[3] = v.w;
        }
    }

    // ---- prefetch chunk 0 ----
    const int sp = tid >> 3;      // pillar for staging (plus sp+32 via u=1)
    const int sj = tid & 7;       // point within chunk
    float2 pf[2];
    #pragma unroll
    for (int u = 0; u < 2; u++) {
        int p = sp + u * 32;
        int gp = base + p;
        pf[u] = make_float2(0.f, 0.f);
        if (gp < M) pf[u] = *(const float2*)(feat + (size_t)gp * 256 + sj * 4 + 2);
    }
    __syncthreads();     // A, Wg, npc ready
    #pragma unroll
    for (int u = 0; u < 2; u++) {
        int p = sp + u * 32;
        stg[p * 9 + sj]       = pf[u].x;
        stg[576 + p * 9 + sj] = pf[u].y;
    }
    __syncthreads();

    // ---- histogram: 8 chunks, double-buffered ----
    const int np = (tid < TILE_P) ? npc[tid] : 0;
    for (int ch = 0; ch < 8; ch++) {
        int cur = ch & 1;
        // issue loads for next chunk (non-blocking until STS)
        if (ch < 7) {
            #pragma unroll
            for (int u = 0; u < 2; u++) {
                int p = sp + u * 32;
                int gp = base + p;
                pf[u] = make_float2(0.f, 0.f);
                if (gp < M)
                    pf[u] = *(const float2*)(feat + (size_t)gp * 256 + ((ch + 1) * 8 + sj) * 4 + 2);
            }
        }
        // hist threads: process current first (their STS of next comes after)
        if (tid < TILE_P) {
            const float* zb = stg + cur * 1152 + tid * 9;
            const float* rb = zb + 576;
            #pragma unroll
            for (int j = 0; j < 8; j++) {
                if (ch * 8 + j < np) {
                    float z = zb[j], r = rb[j];
                    int bin = (int)((z - Z_MIN_F) * INV_BIN);
                    bin = max(0, min(NBINS - 1, bin));
                    float* pc = &A[bin * TILE_P + tid];
                    pc[0]    += 1.0f;
                    pc[4096] += z;
                    pc[8192] += r;
                }
            }
        }
        // store next chunk into the other buffer (no race: nxt != cur)
        if (ch < 7) {
            int nb = (cur ^ 1) * 1152;
            #pragma unroll
            for (int u = 0; u < 2; u++) {
                int p = sp + u * 32;
                stg[nb + p * 9 + sj]       = pf[u].x;
                stg[nb + 576 + p * 9 + sj] = pf[u].y;
            }
        }
        __syncthreads();
    }

    // ---- sums -> means (vectorized) ----
    {
        float4* A4 = (float4*)A;
        #pragma unroll
        for (int i = tid; i < 1024; i += NTHREADS) {
            float4 c4 = A4[i];
            float4 s4 = A4[i + 1024];
            float4 r4 = A4[i + 2048];
            float i0 = __frcp_rn(c4.x + EPS_MEAN);
            float i1 = __frcp_rn(c4.y + EPS_MEAN);
            float i2 = __frcp_rn(c4.z + EPS_MEAN);
            float i3 = __frcp_rn(c4.w + EPS_MEAN);
            s4.x *= i0; s4.y *= i1; s4.z *= i2; s4.w *= i3;
            r4.x *= i0; r4.y *= i1; r4.z *= i2; r4.w *= i3;
            A4[i + 1024] = s4;
            A4[i + 2048] = r4;
        }
    }
    __syncthreads();

    // ---- GEMM: split-K (bins) x (16 pillars x 2 channels)/thread ----
    const int g    = tid >> 7;          // k-group: bins [g*32, g*32+32)
    const int t    = tid & 127;
    const int wg   = t >> 5;            // 0..3
    const int lane = t & 31;
    const int c0   = lane * 2;
    const int p0   = wg * 16;

    u64 acc[8][2];
    if (g == 0) {
        u64 b0 = pack1(bbias[c0]);
        u64 b1 = pack1(bbias[c0 + 1]);
        #pragma unroll
        for (int e = 0; e < 8; e++) { acc[e][0] = b0; acc[e][1] = b1; }
    } else {
        #pragma unroll
        for (int e = 0; e < 8; e++) { acc[e][0] = 0ull; acc[e][1] = 0ull; }
    }

    {
        const float* wB = Wg + c0 * WG_PITCH + g * 96;   // + bin-local*3 + comp
        #pragma unroll
        for (int comp = 0; comp < 3; comp++) {
            const float* aB = A + comp * 4096 + g * 32 * 64 + p0;
            const float* w0 = wB + comp;
            const float* w1 = w0 + WG_PITCH;
            #pragma unroll 4
            for (int b = 0; b < 32; b++) {
                const float* ap = aB + b * 64;
                float4 a0 = *(const float4*)(ap);
                float4 a1 = *(const float4*)(ap + 4);
                float4 a2 = *(const float4*)(ap + 8);
                float4 a3 = *(const float4*)(ap + 12);
                u64 wd0 = pack1(w0[b * 3]);
                u64 wd1 = pack1(w1[b * 3]);
                u64 aa;
                aa = pack2(a0.x, a0.y); fma2(acc[0][0], aa, wd0); fma2(acc[0][1], aa, wd1);
                aa = pack2(a0.z, a0.w); fma2(acc[1][0], aa, wd0); fma2(acc[1][1], aa, wd1);
                aa = pack2(a1.x, a1.y); fma2(acc[2][0], aa, wd0); fma2(acc[2][1], aa, wd1);
                aa = pack2(a1.z, a1.w); fma2(acc[3][0], aa, wd0); fma2(acc[3][1], aa, wd1);
                aa = pack2(a2.x, a2.y); fma2(acc[4][0], aa, wd0); fma2(acc[4][1], aa, wd1);
                aa = pack2(a2.z, a2.w); fma2(acc[5][0], aa, wd0); fma2(acc[5][1], aa, wd1);
                aa = pack2(a3.x, a3.y); fma2(acc[6][0], aa, wd0); fma2(acc[6][1], aa, wd1);
                aa = pack2(a3.z, a3.w); fma2(acc[7][0], aa, wd0); fma2(acc[7][1], aa, wd1);
            }
        }
    }

    // ---- split-K reduce through Wg (dead after GEMM) ----
    __syncthreads();
    float2* scratch = (float2*)Wg;            // [16][128]
    if (g == 1) {
        #pragma unroll
        for (int e = 0; e < 8; e++) {
            #pragma unroll
            for (int c = 0; c < 2; c++) {
                float lo, hi;
                unpack2(acc[e][c], lo, hi);
                scratch[(e * 2 + c) * 128 + t] = make_float2(lo, hi);
            }
        }
    }
    __syncthreads();

    // ---- epilogue (group 0): add partner, store x, BN partials ----
    float s0 = 0.f, s1 = 0.f, q0 = 0.f, q1 = 0.f;
    if (g == 0) {
        float2* gX2 = (float2*)g_X;
        #pragma unroll
        for (int e = 0; e < 8; e++) {
            float lo0, hi0, lo1, hi1;
            unpack2(acc[e][0], lo0, hi0);
            unpack2(acc[e][1], lo1, hi1);
            float2 o0 = scratch[(e * 2 + 0) * 128 + t];
            float2 o1 = scratch[(e * 2 + 1) * 128 + t];
            float xA0 = lo0 + o0.x, xB0 = hi0 + o0.y;   // channel c0,   pillars p0+2e, p0+2e+1
            float xA1 = lo1 + o1.x, xB1 = hi1 + o1.y;   // channel c0+1
            int gpA = base + p0 + 2 * e;
            int gpB = gpA + 1;
            if (gpA < M) {
                gX2[gpA * 32 + lane] = make_float2(xA0, xA1);
                s0 += xA0; q0 += xA0 * xA0;
                s1 += xA1; q1 += xA1 * xA1;
            }
            if (gpB < M) {
                gX2[gpB * 32 + lane] = make_float2(xB0, xB1);
                s0 += xB0; q0 += xB0 * xB0;
                s1 += xB1; q1 += xB1 * xB1;
            }
        }
    }
    // BN reduction via stage area (dead)
    float2* redS = (float2*)stg;    // [4][32]
    float2* redQ = redS + 128;
    if (g == 0) {
        redS[wg * 32 + lane] = make_float2(s0, s1);
        redQ[wg * 32 + lane] = make_float2(q0, q1);
    }
    __syncthreads();
    if (tid < FC) {
        int l = tid >> 1, h = tid & 1;
        float ts = 0.f, tq = 0.f;
        #pragma unroll
        for (int w = 0; w < 4; w++) {
            float2 vs = redS[w * 32 + l];
            float2 vq = redQ[w * 32 + l];
            ts += h ? vs.y : vs.x;
            tq += h ? vq.y : vq.x;
        }
        atomicAdd(&g_sum[tid], ts);
        atomicAdd(&g_sqs[tid], tq);
    }
}

// ---------------- kernel 2: finalize BN scale/shift ----------------
__global__ void finalize_kernel(const float* __restrict__ gamma,
                                const float* __restrict__ beta,
                                int M)
{
    int c = threadIdx.x;
    if (c < FC) {
        float invM = 1.0f / (float)M;
        float mu   = g_sum[c] * invM;
        float var  = g_sqs[c] * invM - mu * mu;
        var = fmaxf(var, 0.0f);
        float sc = gamma[c] * rsqrtf(var + EPS_BN);
        g_scale[c] = sc;
        g_shift[c] = beta[c] - mu * sc;
    }
}

// ---------------- kernel 3: normalize + ReLU + reset accumulators ----------------
__global__ void __launch_bounds__(256)
apply_kernel(float4* __restrict__ out, int M)
{
    int n4 = M * (FC / 4);
    int gid = blockIdx.x * blockDim.x + threadIdx.x;
    int stride = gridDim.x * blockDim.x;

    float4 x[4];
    int idx[4];
    #pragma unroll
    for (int u = 0; u < 4; u++) {
        int i = gid + u * stride;
        idx[u] = i;
        if (i < n4) x[u] = g_X[i];
    }
    #pragma unroll
    for (int u = 0; u < 4; u++) {
        int i = idx[u];
        if (i < n4) {
            int cb = (i & 15) * 4;
            float4 sc = *(const float4*)&g_scale[cb];
            float4 sh = *(const float4*)&g_shift[cb];
            float4 r;
            r.x = fmaxf(fmaf(x[u].x, sc.x, sh.x), 0.0f);
            r.y = fmaxf(fmaf(x[u].y, sc.y, sh.y), 0.0f);
            r.z = fmaxf(fmaf(x[u].z, sc.z, sh.z), 0.0f);
            r.w = fmaxf(fmaf(x[u].w, sc.w, sh.w), 0.0f);
            out[i] = r;
        }
    }
    if (blockIdx.x == 0 && threadIdx.x < FC) {
        g_sum[threadIdx.x] = 0.0f;
        g_sqs[threadIdx.x] = 0.0f;
    }
}

// ---------------- launch ----------------
extern "C" void kernel_launch(void* const* d_in, const int* in_sizes, int n_in,
                              void* d_out, int out_size)
{
    const float* feat  = (const float*)d_in[0];
    const int*   nump  = (const int*)  d_in[1];
    const float* W     = (const float*)d_in[3];
    const float* bbias = (const float*)d_in[4];
    const float* gamma = (const float*)d_in[5];
    const float* beta  = (const float*)d_in[6];
    float4* out = (float4*)d_out;

    int M = in_sizes[1];
    if (M > MCAP) M = MCAP;

    cudaFuncSetAttribute(main_kernel, cudaFuncAttributeMaxDynamicSharedMemorySize, SMEM_BYTES);

    int tiles = (M + TILE_P - 1) / TILE_P;
    main_kernel<<<tiles, NTHREADS, SMEM_BYTES>>>(feat, nump, W, bbias, M);
    finalize_kernel<<<1, 64>>>(gamma, beta, M);
    int n4 = M * (FC / 4);
    int threads_needed = (n4 + 3) / 4;
    int blocks = (threads_needed + 255) / 256;
    apply_kernel<<<blocks, 256>>>(out, M);
}

// round 5
// speedup vs baseline: 1.6413x; 1.0003x over previous
#include <cuda_runtime.h>
#include <cuda_bf16.h>
#include <cstdint>

// ---------------- problem constants ----------------
#define NPTS        64
#define NBINS       64
#define KDIM        192
#define FC          64
#define TILE_P      64
#define NTHREADS    256
#define MCAP        100000
#define Z_MIN_F     (-3.0f)
#define INV_BIN     16.0f
#define EPS_MEAN    1e-5f
#define EPS_BN      1e-5f

#define WG_PITCH 193

// shared layout (floats):
//   Wg    [64][193]                 12352  @ 0
//   A     [192][64]                 12288  @ 12352
//   stage 2 bufs x (z+r) x [64][9]   2304  @ 24640   (also BN-reduce overlay)
//   npc   64 ints                      64  @ 26944
#define SM_WG    0
#define SM_A     12352
#define SM_STG   24640
#define SM_NPC   26944
#define SMEM_FLOATS 27008
#define SMEM_BYTES  (SMEM_FLOATS * 4)   // 108032 -> 2 CTAs/SM

// ---------------- global scratch ----------------
__device__ float4 g_X[MCAP * (FC / 4)];
__device__ float  g_sum[FC];
__device__ float  g_sqs[FC];
__device__ float  g_scale[FC];
__device__ float  g_shift[FC];

// ---------------- f32x2 helpers ----------------
typedef unsigned long long u64;
__device__ __forceinline__ u64 pack1(float a) {
    u64 d;
    asm("mov.b64 %0, {%1, %1};" : "=l"(d) : "r"(__float_as_uint(a)));
    return d;
}
__device__ __forceinline__ void fma2(u64& acc, u64 a, u64 b) {
    asm("fma.rn.f32x2 %0, %1, %2, %0;" : "+l"(acc) : "l"(a), "l"(b));
}
__device__ __forceinline__ void unpack2(u64 v, float& lo, float& hi) {
    unsigned int l, h;
    asm("mov.b64 {%0, %1}, %2;" : "=r"(l), "=r"(h) : "l"(v));
    lo = __uint_as_float(l);
    hi = __uint_as_float(h);
}

// ---------------- kernel 1: fused hist + GEMM + BN partials ----------------
__global__ void __launch_bounds__(NTHREADS, 2)
main_kernel(const float* __restrict__ feat,
            const int*   __restrict__ nump,
            const float* __restrict__ W,
            const float* __restrict__ bbias,
            int M)
{
    extern __shared__ float sm[];
    float* Wg  = sm + SM_WG;
    float* A   = sm + SM_A;
    float* stg = sm + SM_STG;
    int*   npc = (int*)(sm + SM_NPC);

    const int tid  = threadIdx.x;
    const int base = blockIdx.x * TILE_P;

    // ---- zero A ----
    {
        float4 z4 = make_float4(0.f, 0.f, 0.f, 0.f);
        float4* A4 = (float4*)A;
        #pragma unroll
        for (int i = tid; i < (KDIM * TILE_P) / 4; i += NTHREADS) A4[i] = z4;
    }
    if (tid < TILE_P) {
        int gp = base + tid;
        npc[tid] = (gp < M) ? nump[gp] : 0;
    }
    // ---- W: coalesced LDG.128, native [c][k] layout, pitch 193 ----
    {
        const float4* W4 = (const float4*)W;
        #pragma unroll
        for (int i = tid; i < (FC * KDIM) / 4; i += NTHREADS) {
            float4 v = W4[i];
            int c = i / 48;
            int k = (i - c * 48) * 4;
            float* dst = Wg + c * WG_PITCH + k;
            dst[0] = v.x; dst[1] = v.y; dst[2] = v.z; dst[3] = v.w;
        }
    }

    // ---- prefetch chunk 0 ----
    const int sp = tid >> 3;
    const int sj = tid & 7;
    float2 pf[2];
    #pragma unroll
    for (int u = 0; u < 2; u++) {
        int p = sp + u * 32;
        int gp = base + p;
        pf[u] = make_float2(0.f, 0.f);
        if (gp < M) pf[u] = *(const float2*)(feat + (size_t)gp * 256 + sj * 4 + 2);
    }
    __syncthreads();     // A, Wg, npc ready
    #pragma unroll
    for (int u = 0; u < 2; u++) {
        int p = sp + u * 32;
        stg[p * 9 + sj]       = pf[u].x;
        stg[576 + p * 9 + sj] = pf[u].y;
    }
    __syncthreads();

    // ---- histogram: 8 chunks, double-buffered ----
    const int np = (tid < TILE_P) ? npc[tid] : 0;
    for (int ch = 0; ch < 8; ch++) {
        int cur = ch & 1;
        if (ch < 7) {
            #pragma unroll
            for (int u = 0; u < 2; u++) {
                int p = sp + u * 32;
                int gp = base + p;
                pf[u] = make_float2(0.f, 0.f);
                if (gp < M)
                    pf[u] = *(const float2*)(feat + (size_t)gp * 256 + ((ch + 1) * 8 + sj) * 4 + 2);
            }
        }
        if (tid < TILE_P) {
            const float* zb = stg + cur * 1152 + tid * 9;
            const float* rb = zb + 576;
            #pragma unroll
            for (int j = 0; j < 8; j++) {
                if (ch * 8 + j < np) {
                    float z = zb[j], r = rb[j];
                    int bin = (int)((z - Z_MIN_F) * INV_BIN);
                    bin = max(0, min(NBINS - 1, bin));
                    float* pc = &A[bin * TILE_P + tid];
                    // 3 loads first (independent, pipelined), then 3 stores:
                    // exposes ONE smem latency per point instead of three.
                    float c0 = pc[0];
                    float s0 = pc[4096];
                    float r0 = pc[8192];
                    pc[0]    = c0 + 1.0f;
                    pc[4096] = s0 + z;
                    pc[8192] = r0 + r;
                }
            }
        }
        if (ch < 7) {
            int nb = (cur ^ 1) * 1152;
            #pragma unroll
            for (int u = 0; u < 2; u++) {
                int p = sp + u * 32;
                stg[nb + p * 9 + sj]       = pf[u].x;
                stg[nb + 576 + p * 9 + sj] = pf[u].y;
            }
        }
        __syncthreads();
    }

    // ---- sums -> means (vectorized) ----
    {
        float4* A4 = (float4*)A;
        #pragma unroll
        for (int i = tid; i < 1024; i += NTHREADS) {
            float4 c4 = A4[i];
            float4 s4 = A4[i + 1024];
            float4 r4 = A4[i + 2048];
            float i0 = __frcp_rn(c4.x + EPS_MEAN);
            float i1 = __frcp_rn(c4.y + EPS_MEAN);
            float i2 = __frcp_rn(c4.z + EPS_MEAN);
            float i3 = __frcp_rn(c4.w + EPS_MEAN);
            s4.x *= i0; s4.y *= i1; s4.z *= i2; s4.w *= i3;
            r4.x *= i0; r4.y *= i1; r4.z *= i2; r4.w *= i3;
            A4[i + 1024] = s4;
            A4[i + 2048] = r4;
        }
    }
    __syncthreads();

    // ---- GEMM: split-K (bins) x (16 pillars x 2 channels)/thread ----
    const int g    = tid >> 7;
    const int t    = tid & 127;
    const int wg   = t >> 5;
    const int lane = t & 31;
    const int c0   = lane * 2;
    const int p0   = wg * 16;

    u64 acc[8][2];
    if (g == 0) {
        u64 b0 = pack1(bbias[c0]);
        u64 b1 = pack1(bbias[c0 + 1]);
        #pragma unroll
        for (int e = 0; e < 8; e++) { acc[e][0] = b0; acc[e][1] = b1; }
    } else {
        #pragma unroll
        for (int e = 0; e < 8; e++) { acc[e][0] = 0ull; acc[e][1] = 0ull; }
    }

    {
        const float* wB = Wg + c0 * WG_PITCH + g * 96;
        #pragma unroll
        for (int comp = 0; comp < 3; comp++) {
            const float* aB = A + comp * 4096 + g * 32 * 64 + p0;
            const float* w0 = wB + comp;
            const float* w1 = w0 + WG_PITCH;
            #pragma unroll 4
            for (int b = 0; b < 32; b++) {
                // LDS.128 -> ulonglong2: the .x/.y ARE packed f32x2 pairs (no MOVs)
                const ulonglong2* ap2 = (const ulonglong2*)(aB + b * 64);
                ulonglong2 v0 = ap2[0];   // pillars p0+0..3
                ulonglong2 v1 = ap2[1];   // pillars p0+4..7
                ulonglong2 v2 = ap2[2];   // pillars p0+8..11
                ulonglong2 v3 = ap2[3];   // pillars p0+12..15
                u64 wd0 = pack1(w0[b * 3]);
                u64 wd1 = pack1(w1[b * 3]);
                fma2(acc[0][0], v0.x, wd0); fma2(acc[0][1], v0.x, wd1);
                fma2(acc[1][0], v0.y, wd0); fma2(acc[1][1], v0.y, wd1);
                fma2(acc[2][0], v1.x, wd0); fma2(acc[2][1], v1.x, wd1);
                fma2(acc[3][0], v1.y, wd0); fma2(acc[3][1], v1.y, wd1);
                fma2(acc[4][0], v2.x, wd0); fma2(acc[4][1], v2.x, wd1);
                fma2(acc[5][0], v2.y, wd0); fma2(acc[5][1], v2.y, wd1);
                fma2(acc[6][0], v3.x, wd0); fma2(acc[6][1], v3.x, wd1);
                fma2(acc[7][0], v3.y, wd0); fma2(acc[7][1], v3.y, wd1);
            }
        }
    }

    // ---- split-K reduce through Wg (dead after GEMM) ----
    __syncthreads();
    float2* scratch = (float2*)Wg;            // [16][128]
    if (g == 1) {
        #pragma unroll
        for (int e = 0; e < 8; e++) {
            #pragma unroll
            for (int c = 0; c < 2; c++) {
                float lo, hi;
                unpack2(acc[e][c], lo, hi);
                scratch[(e * 2 + c) * 128 + t] = make_float2(lo, hi);
            }
        }
    }
    __syncthreads();

    // ---- epilogue (group 0): add partner, store x, BN partials ----
    float s0 = 0.f, s1 = 0.f, q0 = 0.f, q1 = 0.f;
    if (g == 0) {
        float2* gX2 = (float2*)g_X;
        #pragma unroll
        for (int e = 0; e < 8; e++) {
            float lo0, hi0, lo1, hi1;
            unpack2(acc[e][0], lo0, hi0);
            unpack2(acc[e][1], lo1, hi1);
            float2 o0 = scratch[(e * 2 + 0) * 128 + t];
            float2 o1 = scratch[(e * 2 + 1) * 128 + t];
            float xA0 = lo0 + o0.x, xB0 = hi0 + o0.y;
            float xA1 = lo1 + o1.x, xB1 = hi1 + o1.y;
            int gpA = base + p0 + 2 * e;
            int gpB = gpA + 1;
            if (gpA < M) {
                gX2[gpA * 32 + lane] = make_float2(xA0, xA1);
                s0 += xA0; q0 += xA0 * xA0;
                s1 += xA1; q1 += xA1 * xA1;
            }
            if (gpB < M) {
                gX2[gpB * 32 + lane] = make_float2(xB0, xB1);
                s0 += xB0; q0 += xB0 * xB0;
                s1 += xB1; q1 += xB1 * xB1;
            }
        }
    }
    float2* redS = (float2*)stg;    // [4][32]
    float2* redQ = redS + 128;
    if (g == 0) {
        redS[wg * 32 + lane] = make_float2(s0, s1);
        redQ[wg * 32 + lane] = make_float2(q0, q1);
    }
    __syncthreads();
    if (tid < FC) {
        int l = tid >> 1, h = tid & 1;
        float ts = 0.f, tq = 0.f;
        #pragma unroll
        for (int w = 0; w < 4; w++) {
            float2 vs = redS[w * 32 + l];
            float2 vq = redQ[w * 32 + l];
            ts += h ? vs.y : vs.x;
            tq += h ? vq.y : vq.x;
        }
        atomicAdd(&g_sum[tid], ts);
        atomicAdd(&g_sqs[tid], tq);
    }
}

// ---------------- kernel 2: finalize BN scale/shift ----------------
__global__ void finalize_kernel(const float* __restrict__ gamma,
                                const float* __restrict__ beta,
                                int M)
{
    int c = threadIdx.x;
    if (c < FC) {
        float invM = 1.0f / (float)M;
        float mu   = g_sum[c] * invM;
        float var  = g_sqs[c] * invM - mu * mu;
        var = fmaxf(var, 0.0f);
        float sc = gamma[c] * rsqrtf(var + EPS_BN);
        g_scale[c] = sc;
        g_shift[c] = beta[c] - mu * sc;
    }
}

// ---------------- kernel 3: normalize + ReLU + reset accumulators ----------------
__global__ void __launch_bounds__(256)
apply_kernel(float4* __restrict__ out, int M)
{
    int n4 = M * (FC / 4);
    int gid = blockIdx.x * blockDim.x + threadIdx.x;
    int stride = gridDim.x * blockDim.x;

    float4 x[4];
    int idx[4];
    #pragma unroll
    for (int u = 0; u < 4; u++) {
        int i = gid + u * stride;
        idx[u] = i;
        if (i < n4) x[u] = g_X[i];
    }
    #pragma unroll
    for (int u = 0; u < 4; u++) {
        int i = idx[u];
        if (i < n4) {
            int cb = (i & 15) * 4;
            float4 sc = *(const float4*)&g_scale[cb];
            float4 sh = *(const float4*)&g_shift[cb];
            float4 r;
            r.x = fmaxf(fmaf(x[u].x, sc.x, sh.x), 0.0f);
            r.y = fmaxf(fmaf(x[u].y, sc.y, sh.y), 0.0f);
            r.z = fmaxf(fmaf(x[u].z, sc.z, sh.z), 0.0f);
            r.w = fmaxf(fmaf(x[u].w, sc.w, sh.w), 0.0f);
            out[i] = r;
        }
    }
    if (blockIdx.x == 0 && threadIdx.x < FC) {
        g_sum[threadIdx.x] = 0.0f;
        g_sqs[threadIdx.x] = 0.0f;
    }
}

// ---------------- launch ----------------
extern "C" void kernel_launch(void* const* d_in, const int* in_sizes, int n_in,
                              void* d_out, int out_size)
{
    const float* feat  = (const float*)d_in[0];
    const int*   nump  = (const int*)  d_in[1];
    const float* W     = (const float*)d_in[3];
    const float* bbias = (const float*)d_in[4];
    const float* gamma = (const float*)d_in[5];
    const float* beta  = (const float*)d_in[6];
    float4* out = (float4*)d_out;

    int M = in_sizes[1];
    if (M > MCAP) M = MCAP;

    cudaFuncSetAttribute(main_kernel, cudaFuncAttributeMaxDynamicSharedMemorySize, SMEM_BYTES);

    int tiles = (M + TILE_P - 1) / TILE_P;
    main_kernel<<<tiles, NTHREADS, SMEM_BYTES>>>(feat, nump, W, bbias, M);
    finalize_kernel<<<1, 64>>>(gamma, beta, M);
    int n4 = M * (FC / 4);
    int threads_needed = (n4 + 3) / 4;
    int blocks = (threads_needed + 255) / 256;
    apply_kernel<<<blocks, 256>>>(out, M);
}